// round 4
// baseline (speedup 1.0000x reference)
#include <cuda_runtime.h>

#define GN 100000
#define GE 1600000
#define H0 32
#define H1 8

// ---------------- scratch (static __device__ — no allocations) ----------------
__device__ __align__(16) float g_xw[GN * H0];    // x @ W0
__device__ __align__(16) float g_hacc[GN * H0];  // conv1 edge aggregation
__device__ __align__(16) float g_out[GN * H1];   // conv2 aggregation (no atomics on d_out)
__device__ __align__(16) float g_hw[GN * H1];    // h @ W1
__device__ float g_deg1[GN];       // deg1 -> dinv1 (in place)
__device__ float g_deg2[GN];       // deg2 -> dinv2 (in place)
__device__ float g_s1[GN];
__device__ float g_s2[GN];
__device__ float g_mw[GE];         // masked edge weight
__device__ float g_wa1[H0];
__device__ float g_wa2[H0];
__device__ float g_cbias;
__device__ int   g_is64;           // 1 if edge_idx stored as int64, 0 if int32

// ---------------- helpers ----------------
__device__ __forceinline__ void ffma2(unsigned long long& d, unsigned long long a,
                                      unsigned long long b) {
    asm("fma.rn.f32x2 %0, %1, %2, %0;" : "+l"(d) : "l"(a), "l"(b));
}

// edge-index accessor, dtype decided at runtime
__device__ __forceinline__ int eidx(const void* ei, long long i) {
    if (g_is64) return (int)((const long long*)ei)[i];
    return ((const int*)ei)[i];
}

// ---------------- dtype detection ----------------
// Edge values < 2^17. If stored int64 (little-endian), every odd 32-bit word is 0.
__global__ void k_dtype(const unsigned int* __restrict__ w) {
    if (threadIdx.x == 0) {
        int all0 = 1;
        for (int i = 1; i < 512; i += 2)
            if (w[i] != 0u) { all0 = 0; break; }
        g_is64 = all0;
    }
}

// ---------------- init ----------------
__global__ void k_init() {
    int i = blockIdx.x * blockDim.x + threadIdx.x;
    if (i < GN * H0) g_hacc[i] = 0.f;
    if (i < GN) { g_deg1[i] = 1.f; g_deg2[i] = 1.f; }  // self-loop weight 1
}

// precompute wa1 = Wnb @ Watt[0:8], wa2 = Wself @ Watt[8:16], cbias
__global__ void k_pre(const float* __restrict__ Wnb, const float* __restrict__ bnb,
                      const float* __restrict__ Wself, const float* __restrict__ bself,
                      const float* __restrict__ Watt, const float* __restrict__ batt) {
    int j = threadIdx.x;
    if (j < H0) {
        float a1 = 0.f, a2 = 0.f;
#pragma unroll
        for (int k = 0; k < 8; k++) {
            a1 += Wnb[j * 8 + k] * Watt[k];
            a2 += Wself[j * 8 + k] * Watt[8 + k];
        }
        g_wa1[j] = a1;
        g_wa2[j] = a2;
    }
    if (j == 0) {
        float c = batt[0];
        for (int k = 0; k < 8; k++) c += bnb[k] * Watt[k] + bself[k] * Watt[8 + k];
        g_cbias = c;
    }
}

// ---------------- GEMM: xw = x @ W0  (100000 x 512 x 32), packed f32x2 ----------------
__global__ __launch_bounds__(256) void k_gemm(const float* __restrict__ x,
                                              const float* __restrict__ W0) {
    __shared__ float sX[32][68];    // [kk][row], padded stride
    __shared__ float2 sW[32][32];   // duplicated (w,w) pairs

    const int tid = threadIdx.x;
    const int c = tid & 31;        // output column
    const int wid = tid >> 5;      // 0..7 -> row group
    const int rbase = blockIdx.x * 64;
    const int r0 = wid * 8;

    unsigned long long acc[4];
#pragma unroll
    for (int p = 0; p < 4; p++) acc[p] = 0ull;  // (0.0f, 0.0f)

    const int fr = tid >> 3;  // 0..31
    const int fq = tid & 7;   // 0..7

    for (int k0 = 0; k0 < 512; k0 += 32) {
#pragma unroll
        for (int i = 0; i < 4; i++) {
            int idx = tid + 256 * i;
            int kk = idx >> 5, cc = idx & 31;
            float w = W0[(k0 + kk) * H0 + cc];
            sW[kk][cc] = make_float2(w, w);
        }
#pragma unroll
        for (int pass = 0; pass < 2; pass++) {
            int r = fr + 32 * pass;
            int grow = rbase + r;
            if (grow >= GN) grow = GN - 1;
            float4 v = *reinterpret_cast<const float4*>(x + (size_t)grow * 512 + k0 + fq * 4);
            sX[fq * 4 + 0][r] = v.x;
            sX[fq * 4 + 1][r] = v.y;
            sX[fq * 4 + 2][r] = v.z;
            sX[fq * 4 + 3][r] = v.w;
        }
        __syncthreads();
#pragma unroll
        for (int kk = 0; kk < 32; kk++) {
            unsigned long long w2 = *reinterpret_cast<const unsigned long long*>(&sW[kk][c]);
            const unsigned long long* px =
                reinterpret_cast<const unsigned long long*>(&sX[kk][r0]);
            ffma2(acc[0], px[0], w2);
            ffma2(acc[1], px[1], w2);
            ffma2(acc[2], px[2], w2);
            ffma2(acc[3], px[3], w2);
        }
        __syncthreads();
    }

#pragma unroll
    for (int p = 0; p < 4; p++) {
        float lo = __uint_as_float((unsigned)(acc[p] & 0xFFFFFFFFull));
        float hi = __uint_as_float((unsigned)(acc[p] >> 32));
        int r = rbase + r0 + 2 * p;
        if (r < GN) g_xw[r * H0 + c] = lo;
        if (r + 1 < GN) g_xw[(r + 1) * H0 + c] = hi;
    }
}

// ---------------- degree for conv1 ----------------
__global__ void k_deg1(const void* __restrict__ ei) {
    int e = blockIdx.x * blockDim.x + threadIdx.x;
    if (e >= GE) return;
    int col = eidx(ei, (long long)GE + e);
    atomicAdd(&g_deg1[col], 1.0f);
}

__global__ void k_rsq1() {
    int i = blockIdx.x * blockDim.x + threadIdx.x;
    if (i < GN) g_deg1[i] = rsqrtf(g_deg1[i]);
}
__global__ void k_rsq2() {
    int i = blockIdx.x * blockDim.x + threadIdx.x;
    if (i < GN) g_deg2[i] = rsqrtf(g_deg2[i]);
}

// ---------------- conv1 aggregation: 8 threads / edge, scalar atomics ----------------
__global__ void k_agg1(const void* __restrict__ ei) {
    long long t = (long long)blockIdx.x * blockDim.x + threadIdx.x;
    if (t >= (long long)GE * 8) return;
    int e = (int)(t >> 3), q = (int)(t & 7);
    int row = eidx(ei, e);
    int col = eidx(ei, (long long)GE + e);
    float norm = g_deg1[row] * g_deg1[col];  // dinv1 in place
    float4 v = *reinterpret_cast<const float4*>(&g_xw[row * H0 + q * 4]);
    float* dst = &g_hacc[col * H0 + q * 4];
    atomicAdd(dst + 0, v.x * norm);
    atomicAdd(dst + 1, v.y * norm);
    atomicAdd(dst + 2, v.z * norm);
    atomicAdd(dst + 3, v.w * norm);
}

// ---------------- per-node: h, s1, s2, hw = h @ W1 (warp per node) ----------------
__global__ void k_node(const float* __restrict__ b0, const float* __restrict__ W1) {
    int node = (blockIdx.x * blockDim.x + threadIdx.x) >> 5;
    int lane = threadIdx.x & 31;
    if (node >= GN) return;

    float di = g_deg1[node];  // dinv1
    float h = g_hacc[node * H0 + lane] + g_xw[node * H0 + lane] * di * di + b0[lane];

    float p1 = h * g_wa1[lane];
    float p2 = h * g_wa2[lane];
#pragma unroll
    for (int o = 16; o; o >>= 1) {
        p1 += __shfl_xor_sync(0xFFFFFFFFu, p1, o);
        p2 += __shfl_xor_sync(0xFFFFFFFFu, p2, o);
    }
    if (lane == 0) { g_s1[node] = p1; g_s2[node] = p2; }

    float4 wA = *reinterpret_cast<const float4*>(W1 + lane * 8);
    float4 wB = *reinterpret_cast<const float4*>(W1 + lane * 8 + 4);
    float o0 = h * wA.x, o1 = h * wA.y, o2 = h * wA.z, o3 = h * wA.w;
    float o4 = h * wB.x, o5 = h * wB.y, o6 = h * wB.z, o7 = h * wB.w;
#pragma unroll
    for (int o = 16; o; o >>= 1) {
        o0 += __shfl_xor_sync(0xFFFFFFFFu, o0, o);
        o1 += __shfl_xor_sync(0xFFFFFFFFu, o1, o);
        o2 += __shfl_xor_sync(0xFFFFFFFFu, o2, o);
        o3 += __shfl_xor_sync(0xFFFFFFFFu, o3, o);
        o4 += __shfl_xor_sync(0xFFFFFFFFu, o4, o);
        o5 += __shfl_xor_sync(0xFFFFFFFFu, o5, o);
        o6 += __shfl_xor_sync(0xFFFFFFFFu, o6, o);
        o7 += __shfl_xor_sync(0xFFFFFFFFu, o7, o);
    }
    if (lane == 0) {
        float4* hw4 = reinterpret_cast<float4*>(&g_hw[node * H1]);
        hw4[0] = make_float4(o0, o1, o2, o3);
        hw4[1] = make_float4(o4, o5, o6, o7);
    }
}

// ---------------- edge gate + deg2 ----------------
__global__ void k_gate(const void* __restrict__ ei) {
    int e = blockIdx.x * blockDim.x + threadIdx.x;
    if (e >= GE) return;
    int row = eidx(ei, e);
    int col = eidx(ei, (long long)GE + e);
    float w = g_s1[row] + g_s2[col] + g_cbias;  // pre-relu attention logit
    float mw = 0.f;
    if (w > 0.f) {
        float s = 1.f / (1.f + __expf(-w));       // sigmoid(relu(w)) with w>0
        float mask = fminf(s * 1.01f, 1.f);       // clip(s*(zeta-gamma)+gamma, 0, 1)
        mw = mask * w;
        atomicAdd(&g_deg2[col], mw);
    }
    g_mw[e] = mw;
}

// ---------------- g_out init: self-loop term + bias ----------------
__global__ void k_oinit(const float* __restrict__ b1) {
    int i = blockIdx.x * blockDim.x + threadIdx.x;
    if (i >= GN * H1) return;
    float d = g_deg2[i >> 3];  // dinv2
    g_out[i] = g_hw[i] * d * d + b1[i & 7];
}

// ---------------- conv2 aggregation: 2 threads / edge, scalar atomics ----------------
__global__ void k_agg2(const void* __restrict__ ei) {
    long long t = (long long)blockIdx.x * blockDim.x + threadIdx.x;
    if (t >= (long long)GE * 2) return;
    int e = (int)(t >> 1), q = (int)(t & 1);
    float mw = g_mw[e];
    if (mw == 0.f) return;  // gated off: exact zero contribution
    int row = eidx(ei, e);
    int col = eidx(ei, (long long)GE + e);
    float norm = g_deg2[row] * mw * g_deg2[col];
    float4 v = *reinterpret_cast<const float4*>(&g_hw[row * H1 + q * 4]);
    float* dst = &g_out[col * H1 + q * 4];
    atomicAdd(dst + 0, v.x * norm);
    atomicAdd(dst + 1, v.y * norm);
    atomicAdd(dst + 2, v.z * norm);
    atomicAdd(dst + 3, v.w * norm);
}

// ---------------- final copy: plain stores to harness buffer ----------------
__global__ void k_final(float* __restrict__ out) {
    int i = blockIdx.x * blockDim.x + threadIdx.x;
    if (i < GN * H1 / 4) {
        reinterpret_cast<float4*>(out)[i] = reinterpret_cast<const float4*>(g_out)[i];
    }
}

// ---------------- launch ----------------
extern "C" void kernel_launch(void* const* d_in, const int* in_sizes, int n_in,
                              void* d_out, int out_size) {
    const float* x   = (const float*)d_in[0];
    const void*  ei  = d_in[1];
    const float* W0  = (const float*)d_in[2];
    const float* b0  = (const float*)d_in[3];
    const float* W1  = (const float*)d_in[4];
    const float* b1  = (const float*)d_in[5];
    const float* Wnb = (const float*)d_in[6];
    const float* bnb = (const float*)d_in[7];
    const float* Wself = (const float*)d_in[8];
    const float* bself = (const float*)d_in[9];
    const float* Watt  = (const float*)d_in[10];
    const float* batt  = (const float*)d_in[11];
    float* out = (float*)d_out;

    k_dtype<<<1, 32>>>((const unsigned int*)ei);
    k_init<<<(GN * H0 + 255) / 256, 256>>>();
    k_pre<<<1, 32>>>(Wnb, bnb, Wself, bself, Watt, batt);
    k_gemm<<<(GN + 63) / 64, 256>>>(x, W0);
    k_deg1<<<(GE + 255) / 256, 256>>>(ei);
    k_rsq1<<<(GN + 255) / 256, 256>>>();
    k_agg1<<<(GE * 8 + 255) / 256, 256>>>(ei);
    k_node<<<(GN * 32 + 255) / 256, 256>>>(b0, W1);
    k_gate<<<(GE + 255) / 256, 256>>>(ei);
    k_rsq2<<<(GN + 255) / 256, 256>>>();
    k_oinit<<<(GN * H1 + 255) / 256, 256>>>(b1);
    k_agg2<<<(GE * 2 + 255) / 256, 256>>>(ei);
    k_final<<<(GN * H1 / 4 + 255) / 256, 256>>>(out);
}

// round 5
// speedup vs baseline: 1.5435x; 1.5435x over previous
#include <cuda_runtime.h>

#define GN 100000
#define GE 1600000
#define H0 32
#define H1 8
#define SXS 260   // sX row stride in floats; 260*4=1040 B = 65*16 -> 16B-aligned rows

// ---------------- scratch (static __device__ — no allocations) ----------------
__device__ __align__(16) float g_xw[GN * H0];    // x @ W0
__device__ __align__(16) float g_hacc[GN * H0];  // conv1 edge aggregation
__device__ __align__(16) float g_out[GN * H1];   // conv2 aggregation (no atomics on d_out)
__device__ __align__(16) float g_hw[GN * H1];    // h @ W1
__device__ float g_deg1[GN];       // deg1 -> dinv1 (in place)
__device__ float g_deg2[GN];       // deg2 -> dinv2 (in place)
__device__ float g_s1[GN];
__device__ float g_s2[GN];
__device__ float g_mw[GE];         // masked edge weight
__device__ float g_wa1[H0];
__device__ float g_wa2[H0];
__device__ float g_cbias;
__device__ int   g_is64;           // 1 if edge_idx stored as int64, 0 if int32

// ---------------- helpers ----------------
__device__ __forceinline__ void ffma2(unsigned long long& d, unsigned long long a,
                                      unsigned long long b) {
    asm("fma.rn.f32x2 %0, %1, %2, %0;" : "+l"(d) : "l"(a), "l"(b));
}

// vector red, explicit generic->global conversion (R3 form; 717 fixed, 700 was dtype bug)
__device__ __forceinline__ void red4(float* a, float x, float y, float z, float w) {
    asm volatile(
        "{\n\t"
        ".reg .u64 p;\n\t"
        "cvta.to.global.u64 p, %0;\n\t"
        "red.global.add.v4.f32 [p], {%1,%2,%3,%4};\n\t"
        "}"
        :: "l"(a), "f"(x), "f"(y), "f"(z), "f"(w) : "memory");
}

// edge-index accessor, dtype decided at runtime
__device__ __forceinline__ int eidx(const void* ei, long long i) {
    if (g_is64) return (int)((const long long*)ei)[i];
    return ((const int*)ei)[i];
}

// ---------------- dtype detection ----------------
// Edge values < 2^17. If stored int64 (little-endian), every odd 32-bit word is 0.
__global__ void k_dtype(const unsigned int* __restrict__ w) {
    if (threadIdx.x == 0) {
        int all0 = 1;
        for (int i = 1; i < 512; i += 2)
            if (w[i] != 0u) { all0 = 0; break; }
        g_is64 = all0;
    }
}

// ---------------- init ----------------
__global__ void k_init() {
    int i = blockIdx.x * blockDim.x + threadIdx.x;
    if (i < GN * H0) g_hacc[i] = 0.f;
    if (i < GN) { g_deg1[i] = 1.f; g_deg2[i] = 1.f; }  // self-loop weight 1
}

// precompute wa1 = Wnb @ Watt[0:8], wa2 = Wself @ Watt[8:16], cbias
__global__ void k_pre(const float* __restrict__ Wnb, const float* __restrict__ bnb,
                      const float* __restrict__ Wself, const float* __restrict__ bself,
                      const float* __restrict__ Watt, const float* __restrict__ batt) {
    int j = threadIdx.x;
    if (j < H0) {
        float a1 = 0.f, a2 = 0.f;
#pragma unroll
        for (int k = 0; k < 8; k++) {
            a1 += Wnb[j * 8 + k] * Watt[k];
            a2 += Wself[j * 8 + k] * Watt[8 + k];
        }
        g_wa1[j] = a1;
        g_wa2[j] = a2;
    }
    if (j == 0) {
        float c = batt[0];
        for (int k = 0; k < 8; k++) c += bnb[k] * Watt[k] + bself[k] * Watt[8 + k];
        g_cbias = c;
    }
}

// ---------------- GEMM: xw = x @ W0  (100000 x 512 x 32) ----------------
// Tile: 128 rows x 32 cols per block (128 threads).
// Thread (rg=tid>>4, cg=tid&15): 16 rows x 2 cols, packed f32x2 accumulators.
// x staged transposed in shared with XOR swizzle r ^= 4*((kk>>2)&7):
//   store banks provably conflict-free; 16B load groups stay contiguous/aligned.
__global__ __launch_bounds__(128) void k_gemm(const float* __restrict__ x,
                                              const float* __restrict__ W0) {
    __shared__ __align__(16) float  sX[32 * SXS];   // [kk][row(swizzled)]  ~33.3KB
    __shared__ __align__(16) float2 sW[32 * 32];    // duplicated (w,w)      8KB

    const int tid = threadIdx.x;
    const int rg = tid >> 4;       // 0..7  -> rows rg*16 .. rg*16+15
    const int cg = tid & 15;       // cols 2cg, 2cg+1
    const int rbase = blockIdx.x * 128;

    unsigned long long acc[8][2];
#pragma unroll
    for (int p = 0; p < 8; p++) { acc[p][0] = 0ull; acc[p][1] = 0ull; }

    for (int k0 = 0; k0 < 512; k0 += 32) {
        // stage W chunk (32x32): 8 floats per thread, dup into float2
#pragma unroll
        for (int i = 0; i < 8; i++) {
            int idx = tid + 128 * i;
            int kk = idx >> 5, cc = idx & 31;
            float w = W0[(k0 + kk) * H0 + cc];
            sW[kk * 32 + cc] = make_float2(w, w);
        }
        // stage x chunk (128 rows x 32 k), transposed + swizzled: 8 float4 per thread
#pragma unroll
        for (int i = 0; i < 8; i++) {
            int idx = tid + 128 * i;
            int r = idx >> 3;          // 0..127
            int q = idx & 7;           // k-group
            int grow = rbase + r;
            if (grow >= GN) grow = GN - 1;
            float4 v = *reinterpret_cast<const float4*>(
                x + (size_t)grow * 512 + k0 + 4 * q);
            int rs = r ^ (4 * q);      // swizzle: f(kk)=4*((kk>>2)&7)=4q for kk=4q+j
            sX[(4 * q + 0) * SXS + rs] = v.x;
            sX[(4 * q + 1) * SXS + rs] = v.y;
            sX[(4 * q + 2) * SXS + rs] = v.z;
            sX[(4 * q + 3) * SXS + rs] = v.w;
        }
        __syncthreads();

#pragma unroll
        for (int kk = 0; kk < 32; kk++) {
            ulonglong2 wv = *reinterpret_cast<const ulonglong2*>(&sW[kk * 32 + 2 * cg]);
            const int f = ((kk >> 2) & 7) << 2;   // compile-time const per kk
#pragma unroll
            for (int t = 0; t < 4; t++) {
                ulonglong2 xv = *reinterpret_cast<const ulonglong2*>(
                    &sX[kk * SXS + ((rg * 16 + 4 * t) ^ f)]);
                ffma2(acc[2 * t + 0][0], xv.x, wv.x);
                ffma2(acc[2 * t + 0][1], xv.x, wv.y);
                ffma2(acc[2 * t + 1][0], xv.y, wv.x);
                ffma2(acc[2 * t + 1][1], xv.y, wv.y);
            }
        }
        __syncthreads();
    }

    // write out: acc[p][c] holds rows (16rg+2p, 16rg+2p+1) x col (2cg+c)
#pragma unroll
    for (int p = 0; p < 8; p++) {
        float lo0 = __uint_as_float((unsigned)(acc[p][0] & 0xFFFFFFFFull));
        float hi0 = __uint_as_float((unsigned)(acc[p][0] >> 32));
        float lo1 = __uint_as_float((unsigned)(acc[p][1] & 0xFFFFFFFFull));
        float hi1 = __uint_as_float((unsigned)(acc[p][1] >> 32));
        int r = rbase + rg * 16 + 2 * p;
        if (r < GN)
            *reinterpret_cast<float2*>(&g_xw[r * H0 + 2 * cg]) = make_float2(lo0, lo1);
        if (r + 1 < GN)
            *reinterpret_cast<float2*>(&g_xw[(r + 1) * H0 + 2 * cg]) = make_float2(hi0, hi1);
    }
}

// ---------------- degree for conv1 ----------------
__global__ void k_deg1(const void* __restrict__ ei) {
    int e = blockIdx.x * blockDim.x + threadIdx.x;
    if (e >= GE) return;
    int col = eidx(ei, (long long)GE + e);
    atomicAdd(&g_deg1[col], 1.0f);
}

__global__ void k_rsq1() {
    int i = blockIdx.x * blockDim.x + threadIdx.x;
    if (i < GN) g_deg1[i] = rsqrtf(g_deg1[i]);
}
__global__ void k_rsq2() {
    int i = blockIdx.x * blockDim.x + threadIdx.x;
    if (i < GN) g_deg2[i] = rsqrtf(g_deg2[i]);
}

// ---------------- conv1 aggregation: 8 threads / edge, RED.128 ----------------
__global__ void k_agg1(const void* __restrict__ ei) {
    long long t = (long long)blockIdx.x * blockDim.x + threadIdx.x;
    if (t >= (long long)GE * 8) return;
    int e = (int)(t >> 3), q = (int)(t & 7);
    int row = eidx(ei, e);
    int col = eidx(ei, (long long)GE + e);
    float norm = g_deg1[row] * g_deg1[col];  // dinv1 in place
    float4 v = *reinterpret_cast<const float4*>(&g_xw[row * H0 + q * 4]);
    red4(&g_hacc[col * H0 + q * 4], v.x * norm, v.y * norm, v.z * norm, v.w * norm);
}

// ---------------- per-node: h, s1, s2, hw = h @ W1 (warp per node) ----------------
__global__ void k_node(const float* __restrict__ b0, const float* __restrict__ W1) {
    int node = (blockIdx.x * blockDim.x + threadIdx.x) >> 5;
    int lane = threadIdx.x & 31;
    if (node >= GN) return;

    float di = g_deg1[node];  // dinv1
    float h = g_hacc[node * H0 + lane] + g_xw[node * H0 + lane] * di * di + b0[lane];

    float p1 = h * g_wa1[lane];
    float p2 = h * g_wa2[lane];
#pragma unroll
    for (int o = 16; o; o >>= 1) {
        p1 += __shfl_xor_sync(0xFFFFFFFFu, p1, o);
        p2 += __shfl_xor_sync(0xFFFFFFFFu, p2, o);
    }
    if (lane == 0) { g_s1[node] = p1; g_s2[node] = p2; }

    float4 wA = *reinterpret_cast<const float4*>(W1 + lane * 8);
    float4 wB = *reinterpret_cast<const float4*>(W1 + lane * 8 + 4);
    float o0 = h * wA.x, o1 = h * wA.y, o2 = h * wA.z, o3 = h * wA.w;
    float o4 = h * wB.x, o5 = h * wB.y, o6 = h * wB.z, o7 = h * wB.w;
#pragma unroll
    for (int o = 16; o; o >>= 1) {
        o0 += __shfl_xor_sync(0xFFFFFFFFu, o0, o);
        o1 += __shfl_xor_sync(0xFFFFFFFFu, o1, o);
        o2 += __shfl_xor_sync(0xFFFFFFFFu, o2, o);
        o3 += __shfl_xor_sync(0xFFFFFFFFu, o3, o);
        o4 += __shfl_xor_sync(0xFFFFFFFFu, o4, o);
        o5 += __shfl_xor_sync(0xFFFFFFFFu, o5, o);
        o6 += __shfl_xor_sync(0xFFFFFFFFu, o6, o);
        o7 += __shfl_xor_sync(0xFFFFFFFFu, o7, o);
    }
    if (lane == 0) {
        float4* hw4 = reinterpret_cast<float4*>(&g_hw[node * H1]);
        hw4[0] = make_float4(o0, o1, o2, o3);
        hw4[1] = make_float4(o4, o5, o6, o7);
    }
}

// ---------------- edge gate + deg2 ----------------
__global__ void k_gate(const void* __restrict__ ei) {
    int e = blockIdx.x * blockDim.x + threadIdx.x;
    if (e >= GE) return;
    int row = eidx(ei, e);
    int col = eidx(ei, (long long)GE + e);
    float w = g_s1[row] + g_s2[col] + g_cbias;  // pre-relu attention logit
    float mw = 0.f;
    if (w > 0.f) {
        float s = 1.f / (1.f + __expf(-w));       // sigmoid(relu(w)) with w>0
        float mask = fminf(s * 1.01f, 1.f);       // clip(s*(zeta-gamma)+gamma, 0, 1)
        mw = mask * w;
        atomicAdd(&g_deg2[col], mw);
    }
    g_mw[e] = mw;
}

// ---------------- g_out init: self-loop term + bias ----------------
__global__ void k_oinit(const float* __restrict__ b1) {
    int i = blockIdx.x * blockDim.x + threadIdx.x;
    if (i >= GN * H1) return;
    float d = g_deg2[i >> 3];  // dinv2
    g_out[i] = g_hw[i] * d * d + b1[i & 7];
}

// ---------------- conv2 aggregation: 2 threads / edge, RED.128 ----------------
__global__ void k_agg2(const void* __restrict__ ei) {
    long long t = (long long)blockIdx.x * blockDim.x + threadIdx.x;
    if (t >= (long long)GE * 2) return;
    int e = (int)(t >> 1), q = (int)(t & 1);
    float mw = g_mw[e];
    if (mw == 0.f) return;  // gated off: exact zero contribution
    int row = eidx(ei, e);
    int col = eidx(ei, (long long)GE + e);
    float norm = g_deg2[row] * mw * g_deg2[col];
    float4 v = *reinterpret_cast<const float4*>(&g_hw[row * H1 + q * 4]);
    red4(&g_out[col * H1 + q * 4], v.x * norm, v.y * norm, v.z * norm, v.w * norm);
}

// ---------------- final copy: plain stores to harness buffer ----------------
__global__ void k_final(float* __restrict__ out) {
    int i = blockIdx.x * blockDim.x + threadIdx.x;
    if (i < GN * H1 / 4) {
        reinterpret_cast<float4*>(out)[i] = reinterpret_cast<const float4*>(g_out)[i];
    }
}

// ---------------- launch ----------------
extern "C" void kernel_launch(void* const* d_in, const int* in_sizes, int n_in,
                              void* d_out, int out_size) {
    const float* x   = (const float*)d_in[0];
    const void*  ei  = d_in[1];
    const float* W0  = (const float*)d_in[2];
    const float* b0  = (const float*)d_in[3];
    const float* W1  = (const float*)d_in[4];
    const float* b1  = (const float*)d_in[5];
    const float* Wnb = (const float*)d_in[6];
    const float* bnb = (const float*)d_in[7];
    const float* Wself = (const float*)d_in[8];
    const float* bself = (const float*)d_in[9];
    const float* Watt  = (const float*)d_in[10];
    const float* batt  = (const float*)d_in[11];
    float* out = (float*)d_out;

    k_dtype<<<1, 32>>>((const unsigned int*)ei);
    k_init<<<(GN * H0 + 255) / 256, 256>>>();
    k_pre<<<1, 32>>>(Wnb, bnb, Wself, bself, Watt, batt);
    k_gemm<<<(GN + 127) / 128, 128>>>(x, W0);
    k_deg1<<<(GE + 255) / 256, 256>>>(ei);
    k_rsq1<<<(GN + 255) / 256, 256>>>();
    k_agg1<<<(GE * 8 + 255) / 256, 256>>>(ei);
    k_node<<<(GN * 32 + 255) / 256, 256>>>(b0, W1);
    k_gate<<<(GE + 255) / 256, 256>>>(ei);
    k_rsq2<<<(GN + 255) / 256, 256>>>();
    k_oinit<<<(GN * H1 + 255) / 256, 256>>>(b1);
    k_agg2<<<(GE * 2 + 255) / 256, 256>>>(ei);
    k_final<<<(GN * H1 / 4 + 255) / 256, 256>>>(out);
}